// round 7
// baseline (speedup 1.0000x reference)
#include <cuda_runtime.h>
#include <cstdint>

#define D   128
#define NN  512
#define BB  4
#define RPB 8       // rows per block
#define NPROD 56u   // producer blocks (7 jobs x 8 f-chunks)
#define NBLK  256u

// Scratch (device globals — no allocation allowed)
__device__ float g_part[56 * D];       // W1 fold partials
__device__ float g_r[BB * NN * 4];     // per row: li0, li1, lj0, lj1
__device__ unsigned g_ready   = 0u;    // fold completion counter
__device__ unsigned g_batch[BB] = {0u, 0u, 0u, 0u};  // per-batch row completion
__device__ unsigned g_done    = 0u;    // kernel completion ticket (for reset)

// smem: W2 16384 | h 1024 | Hf 1024 | Wc 512 | p 8 | li 16
#define SMEM_FLOATS (16384 + 1024 + 1024 + 512 + 8 + 16)

// ---------------------------------------------------------------------------
// ONE kernel: W1 fold (blocks 0..55) -> per-row MLP (all blocks)
//             -> per-batch one-way wait -> 8MB logits expand.
// ---------------------------------------------------------------------------
__global__ void __launch_bounds__(256, 2)
fused_kernel(const int*   __restrict__ adj,
             const int*   __restrict__ t,
             const float* __restrict__ TE,
             const float* __restrict__ nc,
             const float* __restrict__ EE,
             const float* __restrict__ W1,
             const float* __restrict__ b1,
             const float* __restrict__ W2,
             const float* __restrict__ b2,
             const float* __restrict__ Wc,
             const float* __restrict__ bc,
             float*       __restrict__ out)
{
    extern __shared__ float smem[];
    float* W2s  = smem;                        // [d*128 + e]
    float* h_s  = smem + 16384;                // [d*8 + r]
    float* Hfs  = smem + 16384 + 1024;         // [r*128 + e]
    float* Wcs  = smem + 16384 + 2048;         // [e*4 + c]
    float* p_s  = smem + 16384 + 2048 + 512;   // [8]
    float* li_s = smem + 16384 + 2048 + 512 + 8; // [8][2] own-row li

    const int tid   = threadIdx.x;
    const int bid   = blockIdx.x;
    const int b     = bid >> 6;
    const int i0    = (bid & 63) * RPB;
    const int grow0 = b * NN + i0;

    const int e    = tid & 127;
    const int g    = tid >> 7;       // 0/1: 4-row group
    const int warp = tid >> 5;       // 0..7
    const int lane = tid & 31;

    // ---- producer role: W1 fold chunk (blocks 0..55) ----
    if (bid < (int)NPROD) {
        __shared__ float s_coef[16];
        const int j  = bid >> 3;     // 0..6
        const int f0 = (bid & 7) * 16;
        if (tid < 16) {
            int f = f0 + tid;
            float v;
            if (j == 0)      v = EE[D + f] - EE[f];
            else if (j == 1) v = EE[f];
            else if (j == 2) v = nc[f];
            else             v = TE[(size_t)t[j - 3] * D + f];
            s_coef[tid] = v;
        }
        __syncthreads();
        if (tid < 128) {
            const int blk = (j <= 1) ? 0 : (j == 2 ? 1 : 2);
            const float* W = W1 + ((size_t)blk * D + f0) * D + tid;
            float acc = 0.f;
#pragma unroll
            for (int f = 0; f < 16; f++)
                acc = fmaf(s_coef[f], W[(size_t)f * D], acc);
            g_part[bid * D + tid] = acc;
            __threadfence();         // release g_part
        }
        __syncthreads();
        if (tid == 0) atomicAdd(&g_ready, 1u);
    }

    // ---- prologue (independent of fold) ----
    {
        const float4* W2_4 = (const float4*)W2;
        float4* W2s_4 = (float4*)W2s;
#pragma unroll
        for (int k = 0; k < 16; k++) W2s_4[tid + k * 256] = W2_4[tid + k * 256];
    }
    if (g == 0) {
        float4 wc = make_float4(Wc[e * 2 + 0], Wc[e * 2 + 1],
                                Wc[(D + e) * 2 + 0], Wc[(D + e) * 2 + 1]);
        *(float4*)(Wcs + e * 4) = wc;
    }
    const float b1e = b1[e];
    const float b2e = b2[e];
    const float bc0 = bc[0], bc1 = bc[1];

    // p: warp w reduces adjacency row w (512 ints = 128 int4, DRAM)
    {
        const int4* a4 = (const int4*)adj + (size_t)grow0 * (NN / 4);
        int s = 0;
#pragma unroll
        for (int k = 0; k < 4; k++) {
            int4 v = a4[warp * 128 + k * 32 + lane];
            s += v.x + v.y + v.z + v.w;
        }
#pragma unroll
        for (int o = 16; o; o >>= 1) s += __shfl_xor_sync(0xffffffffu, s, o);
        if (lane == 0) p_s[warp] = (float)s * (1.0f / 512.0f);
    }

    // ---- wait for fold completion (near-zero: fold << prologue) ----
    if (tid == 0) {
        while (*(volatile unsigned*)&g_ready < NPROD) __nanosleep(64);
        __threadfence();             // acquire
    }
    __syncthreads();

    // Finalize v1/base from partials (32 independent L2-hot loads)
    float v1e   = 0.f;
    float basee = b1e;
#pragma unroll
    for (int c = 0; c < 8; c++) {
        v1e   += g_part[(0 * 8 + c) * D + e];
        basee += g_part[(1 * 8 + c) * D + e]
               + g_part[(2 * 8 + c) * D + e]
               + g_part[((3 + b) * 8 + c) * D + e];
    }

    // h for this thread's 4 rows at element e
    {
        float4 pr = *(const float4*)(p_s + 4 * g);
        float h0 = fmaxf(fmaf(pr.x, v1e, basee), 0.f);
        float h1 = fmaxf(fmaf(pr.y, v1e, basee), 0.f);
        float h2 = fmaxf(fmaf(pr.z, v1e, basee), 0.f);
        float h3 = fmaxf(fmaf(pr.w, v1e, basee), 0.f);
        *(float4*)(h_s + e * 8 + 4 * g) = make_float4(h0, h1, h2, h3);
    }
    __syncthreads();

    // Matvec: Hf[r][e] = relu(sum_d h[r][d] * W2[d][e] + b2[e]), f32x2 pairs
    unsigned long long acc0, acc1;
    {
        unsigned int ub = __float_as_uint(b2e);
        asm("mov.b64 %0, {%1, %1};" : "=l"(acc0) : "r"(ub));
        acc1 = acc0;
    }
#pragma unroll 8
    for (int d = 0; d < D; d++) {
        float w = W2s[d * D + e];
        ulonglong2 hh = *(const ulonglong2*)(h_s + d * 8 + 4 * g);
        unsigned long long w2;
        asm("mov.b64 %0, {%1, %1};" : "=l"(w2) : "r"(__float_as_uint(w)));
        asm("fma.rn.f32x2 %0, %1, %2, %0;" : "+l"(acc0) : "l"(w2), "l"(hh.x));
        asm("fma.rn.f32x2 %0, %1, %2, %0;" : "+l"(acc1) : "l"(w2), "l"(hh.y));
    }
    {
        float2 f0 = *(float2*)&acc0;
        float2 f1 = *(float2*)&acc1;
        Hfs[(4 * g + 0) * D + e] = fmaxf(f0.x, 0.f);
        Hfs[(4 * g + 1) * D + e] = fmaxf(f0.y, 0.f);
        Hfs[(4 * g + 2) * D + e] = fmaxf(f1.x, 0.f);
        Hfs[(4 * g + 3) * D + e] = fmaxf(f1.y, 0.f);
    }
    __syncthreads();

    // Reduction: warp w handles row w, 4 dot products over e
    {
        int r = warp;
        float s0 = 0.f, s1 = 0.f, s2 = 0.f, s3 = 0.f;
#pragma unroll
        for (int k = 0; k < 4; k++) {
            int ee = lane + 32 * k;
            float hv = Hfs[r * D + ee];
            float4 wc = *(const float4*)(Wcs + ee * 4);
            s0 = fmaf(hv, wc.x, s0);
            s1 = fmaf(hv, wc.y, s1);
            s2 = fmaf(hv, wc.z, s2);
            s3 = fmaf(hv, wc.w, s3);
        }
#pragma unroll
        for (int o = 16; o; o >>= 1) {
            s0 += __shfl_xor_sync(0xffffffffu, s0, o);
            s1 += __shfl_xor_sync(0xffffffffu, s1, o);
            s2 += __shfl_xor_sync(0xffffffffu, s2, o);
            s3 += __shfl_xor_sync(0xffffffffu, s3, o);
        }
        if (lane == 0) {
            *(float4*)(g_r + (size_t)(grow0 + r) * 4) = make_float4(s0, s1, s2, s3);
            *(float2*)(li_s + r * 2) = make_float2(s0, s1);   // own li kept local
            __threadfence();                                   // release g_r
        }
    }
    __syncthreads();
    if (tid == 0) atomicAdd(&g_batch[b], 1u);

    // ---- wait only for own batch's 64 row-blocks ----
    if (tid == 0) {
        while (*(volatile unsigned*)&g_batch[b] < 64u) __nanosleep(64);
        __threadfence();             // acquire
    }
    __syncthreads();

    // ---- expand: logits[b,i,j,:] = li[i] + lj[j] + bc (L2-resident write) ----
    float2* lj_s = (float2*)W2s;     // reuse dead W2 smem
#pragma unroll
    for (int k = 0; k < 2; k++) {
        int j = tid + k * 256;
        float2 lj = *(const float2*)(g_r + (size_t)(b * NN + j) * 4 + 2);
        lj_s[j] = make_float2(lj.x + bc0, lj.y + bc1);
    }
    __syncthreads();

    float4* out4 = (float4*)out;
    const float4 a = *(const float4*)(lj_s + 2 * tid);  // (ljx0,ljy0,ljx1,ljy1)
#pragma unroll
    for (int r = 0; r < RPB; r++) {
        int row = b * NN + i0 + r;
        float2 li = *(const float2*)(li_s + r * 2);
        out4[(size_t)row * 256 + tid] =
            make_float4(li.x + a.x, li.y + a.y, li.x + a.z, li.y + a.w);
    }

    // ---- completion ticket: last block resets all flags for next replay ----
    __syncthreads();
    if (tid == 0) {
        __threadfence();
        unsigned tk = atomicAdd(&g_done, 1u);
        if (tk == NBLK - 1u) {
            g_ready = 0u;
            g_batch[0] = 0u; g_batch[1] = 0u; g_batch[2] = 0u; g_batch[3] = 0u;
            g_done = 0u;
            __threadfence();
        }
    }
}

// ---------------------------------------------------------------------------
extern "C" void kernel_launch(void* const* d_in, const int* in_sizes, int n_in,
                              void* d_out, int out_size)
{
    const int*   adj = (const int*)d_in[0];
    const int*   t   = (const int*)d_in[1];
    const float* TE  = (const float*)d_in[2];
    const float* nc  = (const float*)d_in[3];
    const float* EE  = (const float*)d_in[4];
    const float* W1  = (const float*)d_in[5];
    const float* b1  = (const float*)d_in[6];
    const float* W2  = (const float*)d_in[7];
    const float* b2  = (const float*)d_in[8];
    const float* Wc  = (const float*)d_in[9];
    const float* bc  = (const float*)d_in[10];
    float* out = (float*)d_out;

    (void)in_sizes; (void)n_in; (void)out_size;

    const int smem_b = SMEM_FLOATS * sizeof(float);
    cudaFuncSetAttribute(fused_kernel, cudaFuncAttributeMaxDynamicSharedMemorySize, smem_b);

    fused_kernel<<<NBLK, 256, smem_b>>>(adj, t, TE, nc, EE, W1, b1, W2, b2, Wc, bc, out);
}

// round 8
// speedup vs baseline: 1.1404x; 1.1404x over previous
#include <cuda_runtime.h>
#include <cstdint>

#define D     128
#define NN    512
#define BB    4
#define ROWS  16      // rows per row-kernel block
#define EH    64      // e-columns per block (half of D)
#define NPROD 56u     // producer blocks (7 jobs x 8 f-chunks)
#define NBLK1 256u    // row kernel grid (128 row-blocks x 2 halves)

// Scratch (device globals — no allocation allowed)
__device__ float g_part[56 * D];          // W1 fold partials
__device__ float g_r2[2][BB * NN * 4];    // per half, per row: li0 li1 lj0 lj1 (partial)
__device__ unsigned g_ready = 0u;         // fold completion counter (reset in expand)

// smem floats: W2 half 8192 | h 2048 | Hf 1024 | Wc 256 | p 16
#define OFF_W2 0
#define OFF_H  8192
#define OFF_HF (8192 + 2048)
#define OFF_WC (8192 + 2048 + 1024)
#define OFF_P  (8192 + 2048 + 1024 + 256)
#define SMEM_FLOATS (8192 + 2048 + 1024 + 256 + 16)

// ---------------------------------------------------------------------------
// Kernel 1: W1 fold (blocks 0..55, one-way flag) + per-row MLP.
// Block = (rowblk of 16 rows) x (e-half of 64 cols). Writes partial li/lj.
// ---------------------------------------------------------------------------
__global__ void __launch_bounds__(256, 3)
row_kernel(const int*   __restrict__ adj,
           const int*   __restrict__ t,
           const float* __restrict__ TE,
           const float* __restrict__ nc,
           const float* __restrict__ EE,
           const float* __restrict__ W1,
           const float* __restrict__ b1,
           const float* __restrict__ W2,
           const float* __restrict__ b2,
           const float* __restrict__ Wc)
{
    extern __shared__ float smem[];
    float* W2s = smem + OFF_W2;   // [d][e<64]
    float* h_s = smem + OFF_H;    // [d][r<16]
    float* Hfs = smem + OFF_HF;   // [r][e<64]
    float* Wcs = smem + OFF_WC;   // [e<64][4]
    float* p_s = smem + OFF_P;    // [16]

    const int tid  = threadIdx.x;
    const int bid  = blockIdx.x;
    const int half = bid & 1;
    const int rb   = bid >> 1;            // 0..127
    const int b    = rb >> 5;
    const int i0   = (rb & 31) * ROWS;
    const int grow0 = b * NN + i0;
    const int e0   = half * EH;

    const int warp = tid >> 5;
    const int lane = tid & 31;
    const int e    = tid & 63;            // output column within half
    const int rg   = tid >> 6;            // 0..3 -> 4-row group (warp-uniform)

    // ---- producer role: W1 fold chunk (blocks 0..55) ----
    if (bid < (int)NPROD) {
        __shared__ float s_coef[16];
        const int j  = bid >> 3;          // 0..6
        const int f0 = (bid & 7) * 16;
        if (tid < 16) {
            int f = f0 + tid;
            float v;
            if (j == 0)      v = EE[D + f] - EE[f];
            else if (j == 1) v = EE[f];
            else if (j == 2) v = nc[f];
            else             v = TE[(size_t)t[j - 3] * D + f];
            s_coef[tid] = v;
        }
        __syncthreads();
        if (tid < 128) {
            const int blk = (j <= 1) ? 0 : (j == 2 ? 1 : 2);
            const float* W = W1 + ((size_t)blk * D + f0) * D + tid;
            float acc = 0.f;
#pragma unroll
            for (int f = 0; f < 16; f++)
                acc = fmaf(s_coef[f], W[(size_t)f * D], acc);
            g_part[bid * D + tid] = acc;
            __threadfence();              // release g_part
        }
        __syncthreads();
        if (tid == 0) atomicAdd(&g_ready, 1u);
    }

    // ---- prologue (independent of fold) ----
    // Stage half of W2: W2s[d][e] for e in [e0, e0+64). 8 float4 per thread.
    {
        const float4* W2_4 = (const float4*)W2;     // row = 32 float4
        float4* W2s_4 = (float4*)W2s;               // row = 16 float4
#pragma unroll
        for (int k = 0; k < 8; k++) {
            int idx = k * 256 + tid;                // d*16 + q
            int d = idx >> 4, q = idx & 15;
            W2s_4[idx] = W2_4[d * 32 + half * 16 + q];
        }
    }
    if (tid < 64) {
        int ec = e0 + tid;
        float4 wc = make_float4(Wc[ec * 2 + 0], Wc[ec * 2 + 1],
                                Wc[(D + ec) * 2 + 0], Wc[(D + ec) * 2 + 1]);
        *(float4*)(Wcs + tid * 4) = wc;
    }
    const float b2e = b2[e0 + e];

    // p: warp w reduces rows 2w, 2w+1 (each 512 ints = 128 int4)
    {
#pragma unroll
        for (int rr = 0; rr < 2; rr++) {
            int row = 2 * warp + rr;
            const int4* a4 = (const int4*)adj + (size_t)(grow0 + row) * (NN / 4);
            int s = 0;
#pragma unroll
            for (int k = 0; k < 4; k++) {
                int4 v = a4[k * 32 + lane];
                s += v.x + v.y + v.z + v.w;
            }
#pragma unroll
            for (int o = 16; o; o >>= 1) s += __shfl_xor_sync(0xffffffffu, s, o);
            if (lane == 0) p_s[row] = (float)s * (1.0f / 512.0f);
        }
    }

    // ---- wait for fold completion (near-zero: fold << prologue) ----
    if (tid == 0) {
        while (*(volatile unsigned*)&g_ready < NPROD) __nanosleep(64);
        __threadfence();                  // acquire
    }
    __syncthreads();

    // Finalize v1/base at hidden dim d = tid&127 (both thread-halves redundantly),
    // then build h[r][d] for 8 rows each.
    {
        const int d  = tid & 127;
        const int rh = tid >> 7;          // 0/1: row half
        float v1d   = 0.f;
        float based = b1[d];
#pragma unroll
        for (int c = 0; c < 8; c++) {
            v1d   += g_part[(0 * 8 + c) * D + d];
            based += g_part[(1 * 8 + c) * D + d]
                   + g_part[(2 * 8 + c) * D + d]
                   + g_part[((3 + b) * 8 + c) * D + d];
        }
        float hv[8];
#pragma unroll
        for (int r = 0; r < 8; r++)
            hv[r] = fmaxf(fmaf(p_s[rh * 8 + r], v1d, based), 0.f);
        float4* dst = (float4*)(h_s + d * ROWS + rh * 8);
        dst[0] = make_float4(hv[0], hv[1], hv[2], hv[3]);
        dst[1] = make_float4(hv[4], hv[5], hv[6], hv[7]);
    }
    __syncthreads();

    // Matvec: Hf[r][e] = relu(sum_d h[r][d]*W2[d][e0+e] + b2), 4 rows via f32x2
    unsigned long long acc0, acc1;
    {
        unsigned int ub = __float_as_uint(b2e);
        asm("mov.b64 %0, {%1, %1};" : "=l"(acc0) : "r"(ub));
        acc1 = acc0;
    }
#pragma unroll 8
    for (int d = 0; d < D; d++) {
        float w = W2s[d * EH + e];
        ulonglong2 hh = *(const ulonglong2*)(h_s + d * ROWS + rg * 4); // warp-uniform bcast
        unsigned long long w2;
        asm("mov.b64 %0, {%1, %1};" : "=l"(w2) : "r"(__float_as_uint(w)));
        asm("fma.rn.f32x2 %0, %1, %2, %0;" : "+l"(acc0) : "l"(w2), "l"(hh.x));
        asm("fma.rn.f32x2 %0, %1, %2, %0;" : "+l"(acc1) : "l"(w2), "l"(hh.y));
    }
    {
        float2 f0 = *(float2*)&acc0;
        float2 f1 = *(float2*)&acc1;
        Hfs[(rg * 4 + 0) * EH + e] = fmaxf(f0.x, 0.f);
        Hfs[(rg * 4 + 1) * EH + e] = fmaxf(f0.y, 0.f);
        Hfs[(rg * 4 + 2) * EH + e] = fmaxf(f1.x, 0.f);
        Hfs[(rg * 4 + 3) * EH + e] = fmaxf(f1.y, 0.f);
    }
    __syncthreads();

    // Reduce: warp w handles rows 2w, 2w+1; partial (64-col) dots vs Wc halves
    {
#pragma unroll
        for (int rr = 0; rr < 2; rr++) {
            int r = 2 * warp + rr;
            float hv0 = Hfs[r * EH + lane];
            float hv1 = Hfs[r * EH + lane + 32];
            float4 w0 = *(const float4*)(Wcs + lane * 4);
            float4 w1 = *(const float4*)(Wcs + (lane + 32) * 4);
            float s0 = fmaf(hv0, w0.x, hv1 * w1.x);
            float s1 = fmaf(hv0, w0.y, hv1 * w1.y);
            float s2 = fmaf(hv0, w0.z, hv1 * w1.z);
            float s3 = fmaf(hv0, w0.w, hv1 * w1.w);
#pragma unroll
            for (int o = 16; o; o >>= 1) {
                s0 += __shfl_xor_sync(0xffffffffu, s0, o);
                s1 += __shfl_xor_sync(0xffffffffu, s1, o);
                s2 += __shfl_xor_sync(0xffffffffu, s2, o);
                s3 += __shfl_xor_sync(0xffffffffu, s3, o);
            }
            if (lane == 0)
                *(float4*)(&g_r2[half][(size_t)(grow0 + r) * 4]) =
                    make_float4(s0, s1, s2, s3);
        }
    }
}

// ---------------------------------------------------------------------------
// Kernel 2: logits[b,i,j,:] = li[b,i] + lj[b,j] + bc, li/lj = sum of halves.
// Grid 1024 blocks (2 rows each) x 256 threads -> high occupancy stream write.
// ---------------------------------------------------------------------------
__global__ void expand_kernel(const float* __restrict__ bc,
                              float* __restrict__ out)
{
    __shared__ float2 lj_s[NN];
    const int tid = threadIdx.x;
    const int b   = blockIdx.x >> 8;
    const int i0  = (blockIdx.x & 255) * 2;

    if (blockIdx.x == 0 && tid == 0) g_ready = 0u;   // reset for next replay

    const float bc0 = bc[0], bc1 = bc[1];
#pragma unroll
    for (int k = 0; k < 2; k++) {
        int j = tid + k * 256;
        size_t idx = (size_t)(b * NN + j) * 4 + 2;
        float2 a0 = *(const float2*)(&g_r2[0][idx]);
        float2 a1 = *(const float2*)(&g_r2[1][idx]);
        lj_s[j] = make_float2(a0.x + a1.x + bc0, a0.y + a1.y + bc1);
    }
    __syncthreads();

    float4* out4 = (float4*)out;
    const float4 a = *(const float4*)(lj_s + 2 * tid);  // (ljx0,ljy0,ljx1,ljy1)
#pragma unroll
    for (int r = 0; r < 2; r++) {
        int row = b * NN + i0 + r;
        float2 l0 = *(const float2*)(&g_r2[0][(size_t)row * 4]);
        float2 l1 = *(const float2*)(&g_r2[1][(size_t)row * 4]);
        float li0 = l0.x + l1.x, li1 = l0.y + l1.y;
        out4[(size_t)row * 256 + tid] =
            make_float4(li0 + a.x, li1 + a.y, li0 + a.z, li1 + a.w);
    }
}

// ---------------------------------------------------------------------------
extern "C" void kernel_launch(void* const* d_in, const int* in_sizes, int n_in,
                              void* d_out, int out_size)
{
    const int*   adj = (const int*)d_in[0];
    const int*   t   = (const int*)d_in[1];
    const float* TE  = (const float*)d_in[2];
    const float* nc  = (const float*)d_in[3];
    const float* EE  = (const float*)d_in[4];
    const float* W1  = (const float*)d_in[5];
    const float* b1  = (const float*)d_in[6];
    const float* W2  = (const float*)d_in[7];
    const float* b2  = (const float*)d_in[8];
    const float* Wc  = (const float*)d_in[9];
    const float* bc  = (const float*)d_in[10];
    float* out = (float*)d_out;

    (void)in_sizes; (void)n_in; (void)out_size;

    const int smem_b = SMEM_FLOATS * sizeof(float);
    cudaFuncSetAttribute(row_kernel, cudaFuncAttributeMaxDynamicSharedMemorySize, smem_b);

    row_kernel<<<NBLK1, 256, smem_b>>>(adj, t, TE, nc, EE, W1, b1, W2, b2, Wc);
    expand_kernel<<<1024, 256>>>(bc, out);
}